// round 13
// baseline (speedup 1.0000x reference)
#include <cuda_runtime.h>
#include <cstdint>

// Conv2d: x[3,2048,2048] fp32 * k[16,3,3,3] fp32, pad=1, stride=1 -> out[16,2048,2048]
//
// R12 (v8): implicit-GEMM on tensor cores, mma.sync.m16n8k8.tf32, 3xTF32 precision.
//   D[16px, 8oc] = A[16px, K=32] x B[K=32, 8oc],  K = ic*9+kh*3+kw (27 taps, 5 pad).
//   - 3xTF32: x = hi+lo, w = whi+wlo;  D = hi*whi + hi*wlo + lo*whi  (rel_err ~2e-7).
//   - CTA 256 thr = 8 warps; tile 8 rows x 128 cols x 16 oc. Warp w owns output row w,
//     iterates 8 groups of 16 pixels; per group: 2 oc-halves x 4 k-chunks x 3 splits
//     = 24 HMMA, 32 A-gather LDS.32, 16 STG.32.
//   - A gathered straight from the staged (hi,lo) input tile; K-padding + tap decode
//     folded into per-thread base offsets; masked taps read a dedicated zero row.
//   - B (weights) converted once into 32 registers, reused for all groups.

#define HW    2048
#define PLANE (2048 * 2048)

// smem tile: [split][word]; tile = 3 ic x 10 rows x 132 cols = 3960 words,
// zero row at words 3960..4111 (covers base 3960 + px0(<=112) + r(<=7) + 8).
#define TROW   132
#define TIC    1320            // 10 * 132
#define TSIZE  3960
#define ZBASE  3960
#define TWORDS 4112

__device__ __forceinline__ unsigned f2tf32(float v) {
    unsigned r;
    asm("cvt.rna.tf32.f32 %0, %1;" : "=r"(r) : "f"(v));
    return r;
}

__device__ __forceinline__ void mma_tf32(float* c, const unsigned* a,
                                         unsigned b0, unsigned b1) {
    asm volatile(
        "mma.sync.aligned.m16n8k8.row.col.f32.tf32.tf32.f32 "
        "{%0,%1,%2,%3}, {%4,%5,%6,%7}, {%8,%9}, {%0,%1,%2,%3};"
        : "+f"(c[0]), "+f"(c[1]), "+f"(c[2]), "+f"(c[3])
        : "r"(a[0]), "r"(a[1]), "r"(a[2]), "r"(a[3]), "r"(b0), "r"(b1));
}

__global__ __launch_bounds__(256, 3)
void conv3x3_tf32_mma_kernel(const float* __restrict__ x,
                             const float* __restrict__ kern,
                             float* __restrict__ out) {
    __shared__ unsigned s_t[2][TWORDS];     // [0]=hi, [1]=lo

    const int tid  = threadIdx.x;
    const int bx   = blockIdx.x;            // 16 tiles of 128 cols
    const int by   = blockIdx.y;            // 256 tiles of 8 rows
    const int row0 = by * 8 - 1;
    const int col0 = bx * 128 - 1;
    const int wid  = tid >> 5;              // warp = output row within tile (0..7)
    const int lane = tid & 31;
    const int lq   = lane & 3;
    const int lr   = lane >> 2;

    // ---- Stage input tile (3 x 10 x 130), split into tf32 hi/lo ----
    for (int i = tid; i < 3900; i += 256) {
        int ic  = i / 1300;
        int rem = i - ic * 1300;
        int r   = rem / 130;
        int c   = rem - r * 130;
        int gy = row0 + r;
        int gx = col0 + c;
        float v = 0.0f;
        if ((unsigned)gy < (unsigned)HW && (unsigned)gx < (unsigned)HW)
            v = x[ic * PLANE + gy * HW + gx];
        unsigned hb = f2tf32(v);
        float    hf = __uint_as_float(hb);
        unsigned lb = f2tf32(v - hf);
        int off = ic * TIC + r * TROW + c;
        s_t[0][off] = hb;
        s_t[1][off] = lb;
    }
    // zero rows (masked-tap target)
    if (tid < TWORDS - ZBASE) {
        s_t[0][ZBASE + tid] = 0u;
        s_t[1][ZBASE + tid] = 0u;
    }

    // ---- B fragments in registers: bh/bl[chunk][sel][ochalf] ----
    // B[k][n]: b_sel0 covers k = 8c + lq, b_sel1 covers k = 8c + 4 + lq; n = 8h + lr.
    unsigned bh[4][2][2], bl[4][2][2];
    #pragma unroll
    for (int c = 0; c < 4; ++c)
        #pragma unroll
        for (int s = 0; s < 2; ++s) {
            int k = 8 * c + 4 * s + lq;
            #pragma unroll
            for (int h = 0; h < 2; ++h) {
                int oc = 8 * h + lr;
                float w = (k < 27) ? kern[oc * 27 + k] : 0.0f;
                unsigned whb = f2tf32(w);
                float    whf = __uint_as_float(whb);
                bh[c][s][h] = whb;
                bl[c][s][h] = f2tf32(w - whf);
            }
        }

    // ---- A base offsets: base[chunk][sel] (tap decode folded in) ----
    int base[4][2];
    #pragma unroll
    for (int c = 0; c < 4; ++c)
        #pragma unroll
        for (int s = 0; s < 2; ++s) {
            int k = 8 * c + 4 * s + lq;
            if (k < 27) {
                int ic = k / 9;
                int rm = k - ic * 9;
                int kh = rm / 3;
                int kw = rm - kh * 3;
                base[c][s] = ic * TIC + (wid + kh) * TROW + kw;
            } else {
                base[c][s] = ZBASE;
            }
        }

    __syncthreads();

    const int Y = by * 8 + wid;

    // ---- 8 groups of 16 pixels ----
    #pragma unroll
    for (int g = 0; g < 8; ++g) {
        const int px0 = g * 16;
        float acc[2][4];
        #pragma unroll
        for (int h = 0; h < 2; ++h)
            #pragma unroll
            for (int i = 0; i < 4; ++i) acc[h][i] = 0.0f;

        #pragma unroll
        for (int c = 0; c < 4; ++c) {
            // A fragment: a0:(r, k_s0) a1:(r+8, k_s0) a2:(r, k_s1) a3:(r+8, k_s1)
            int i0 = base[c][0] + px0 + lr;
            int i1 = base[c][1] + px0 + lr;
            unsigned ah[4], al[4];
            ah[0] = s_t[0][i0];     ah[1] = s_t[0][i0 + 8];
            ah[2] = s_t[0][i1];     ah[3] = s_t[0][i1 + 8];
            al[0] = s_t[1][i0];     al[1] = s_t[1][i0 + 8];
            al[2] = s_t[1][i1];     al[3] = s_t[1][i1 + 8];

            #pragma unroll
            for (int h = 0; h < 2; ++h) {
                mma_tf32(acc[h], ah, bh[c][0][h], bh[c][1][h]);  // hi * whi
                mma_tf32(acc[h], ah, bl[c][0][h], bl[c][1][h]);  // hi * wlo
                mma_tf32(acc[h], al, bh[c][0][h], bh[c][1][h]);  // lo * whi
            }
        }

        // ---- Store: c0:(r, 2q) c1:(r, 2q+1) c2:(r+8, 2q) c3:(r+8, 2q+1) ----
        const int X = bx * 128 + px0 + lr;
        #pragma unroll
        for (int h = 0; h < 2; ++h) {
            float* p = out + (8 * h + 2 * lq) * PLANE + Y * HW + X;
            p[0]         = acc[h][0];
            p[PLANE]     = acc[h][1];
            p[8]         = acc[h][2];
            p[PLANE + 8] = acc[h][3];
        }
    }
}

extern "C" void kernel_launch(void* const* d_in, const int* in_sizes, int n_in,
                              void* d_out, int out_size) {
    const float* x = (const float*)d_in[0];   // [3, 2048, 2048]
    const float* k = (const float*)d_in[1];   // [16, 3, 3, 3]
    float* out     = (float*)d_out;           // [16, 2048, 2048]

    dim3 grid(HW / 128, HW / 8);              // (16, 256)
    conv3x3_tf32_mma_kernel<<<grid, 256>>>(x, k, out);
}

// round 14
// speedup vs baseline: 1.0951x; 1.0951x over previous
#include <cuda_runtime.h>
#include <cuda_bf16.h>
#include <cstdint>

// Conv2d: x[3,2048,2048] fp32 * k[16,3,3,3] fp32, pad=1, stride=1 -> out[16,2048,2048]
//
// R13 (v9): implicit-GEMM, mma.sync bf16 (m16n8k16 + m16n8k8 tail), 3-term bf16 split.
//   K-axis permuted into pairs: p0..p8 = (kw0,kw1) taps of (ic,kh) -> ONE pre-paired
//   bf16x2 smem slot; p9..p17 = (kw2, junk) with the junk lane's weight = 0.
//   K = 36 slots -> per (group,h): 2 x k16 + 1 x k8 per term, 3 terms.
//   D = hi*whi + hi*wlo + lo*whi  (bf16 hi/lo split, rel_err ~2e-5).
//   CTA 256 thr = 8 warps, tile 8 rows x 128 cols x 16 oc; warp = row, 8 groups x 16 px.
//   Split accumulators (accA = hi*whi, accB = cross) shorten HMMA chains.
//   __launch_bounds__(256,4) -> 64 regs, 4 CTAs (31.7KB smem each) = 32 warps/SM.

#define HW    2048
#define PLANE (2048 * 2048)
#define TROW  132            // pair slots per row
#define TIC   1320           // 10 * TROW
#define TPAD  3968           // words per split array (3*TIC = 3960, padded)

__device__ __forceinline__ void mma16(float* c, const unsigned* a,
                                      unsigned b0, unsigned b1) {
    asm volatile(
        "mma.sync.aligned.m16n8k16.row.col.f32.bf16.bf16.f32 "
        "{%0,%1,%2,%3}, {%4,%5,%6,%7}, {%8,%9}, {%0,%1,%2,%3};"
        : "+f"(c[0]), "+f"(c[1]), "+f"(c[2]), "+f"(c[3])
        : "r"(a[0]), "r"(a[1]), "r"(a[2]), "r"(a[3]), "r"(b0), "r"(b1));
}

__device__ __forceinline__ void mma8(float* c, const unsigned* a, unsigned b0) {
    asm volatile(
        "mma.sync.aligned.m16n8k8.row.col.f32.bf16.bf16.f32 "
        "{%0,%1,%2,%3}, {%4,%5}, {%6}, {%0,%1,%2,%3};"
        : "+f"(c[0]), "+f"(c[1]), "+f"(c[2]), "+f"(c[3])
        : "r"(a[0]), "r"(a[1]), "r"(b0));
}

// Weight pair p for output channel oc: packed bf16x2 (hi part, lo part).
// p<9: (kw0,kw1) of (ic,kh); 9<=p<18: (kw2, 0); p>=18: (0,0).
__device__ __forceinline__ void wpair(const float* kern, int p, int oc,
                                      unsigned& bh, unsigned& bl) {
    float wa = 0.0f, wb = 0.0f;
    if (p < 9) {
        int ic = p / 3, kh = p - 3 * ic;
        const float* kp = kern + oc * 27 + ic * 9 + kh * 3;
        wa = kp[0];
        wb = kp[1];
    } else if (p < 18) {
        int q = p - 9;
        int ic = q / 3, kh = q - 3 * ic;
        wa = kern[oc * 27 + ic * 9 + kh * 3 + 2];
    }
    __nv_bfloat16 wah = __float2bfloat16(wa);
    __nv_bfloat16 wbh = __float2bfloat16(wb);
    unsigned la = __bfloat16_as_ushort(__float2bfloat16(wa - __bfloat162float(wah)));
    unsigned lb = __bfloat16_as_ushort(__float2bfloat16(wb - __bfloat162float(wbh)));
    bh = (unsigned)__bfloat16_as_ushort(wah)
       | ((unsigned)__bfloat16_as_ushort(wbh) << 16);
    bl = la | (lb << 16);
}

__global__ __launch_bounds__(256, 4)
void conv3x3_bf16_mma_kernel(const float* __restrict__ x,
                             const float* __restrict__ kern,
                             float* __restrict__ out) {
    // Pair tile: slot s = (bf16(v[s]), bf16(v[s+1])); [0..TPAD) = hi, [TPAD..) = lo.
    __shared__ unsigned s_pair[2 * TPAD];

    const int tid  = threadIdx.x;
    const int bx   = blockIdx.x;            // 16 tiles of 128 cols
    const int by   = blockIdx.y;            // 256 tiles of 8 rows
    const int row0 = by * 8 - 1;
    const int col0 = bx * 128 - 1;
    const int wid  = tid >> 5;              // warp = output row in tile (0..7)
    const int lane = tid & 31;
    const int lq   = lane & 3;
    const int lr   = lane >> 2;

    // ---- B fragments (gmem only; before the sync) ----
    // Bh/Bl[chunk][h][reg]: chunk0 = pairs lq & lq+4, chunk1 = 8+lq & 12+lq.
    unsigned Bh[2][2][2], Bl[2][2][2], B2h[2], B2l[2];
    #pragma unroll
    for (int cb = 0; cb < 2; ++cb)
        #pragma unroll
        for (int h = 0; h < 2; ++h) {
            wpair(kern, 8 * cb + lq,     8 * h + lr, Bh[cb][h][0], Bl[cb][h][0]);
            wpair(kern, 8 * cb + 4 + lq, 8 * h + lr, Bh[cb][h][1], Bl[cb][h][1]);
        }
    #pragma unroll
    for (int h = 0; h < 2; ++h)
        wpair(kern, 16 + lq, 8 * h + lr, B2h[h], B2l[h]);   // lq>=2 -> zeros

    // ---- Stage input tile as bf16 hi/lo adjacent pairs (3 x 10 x 131 values) ----
    {
        unsigned short* sh = reinterpret_cast<unsigned short*>(s_pair);
        for (int i = tid; i < 3930; i += 256) {
            int ic  = i / 1310;
            int rem = i - ic * 1310;
            int r   = rem / 131;
            int c   = rem - r * 131;        // 0..130
            int gy = row0 + r;
            int gx = col0 + c;
            float v = 0.0f;
            if ((unsigned)gy < (unsigned)HW && (unsigned)gx < (unsigned)HW)
                v = x[ic * PLANE + gy * HW + gx];
            __nv_bfloat16 hb = __float2bfloat16(v);
            unsigned short hu = __bfloat16_as_ushort(hb);
            unsigned short lu = __bfloat16_as_ushort(
                __float2bfloat16(v - __bfloat162float(hb)));
            int e = (ic * TIC + r * TROW + c) * 2;   // ushort index, lo-half of slot c
            sh[e] = hu;
            sh[e + 2 * TPAD] = lu;
            if (c > 0) {                              // hi-half of slot c-1
                sh[e - 1] = hu;
                sh[e - 1 + 2 * TPAD] = lu;
            }
        }
    }

    // ---- A base offsets (word index incl. +lr) for this thread's 5 pair rows ----
    auto pbase = [&](int p) -> int {
        if (p >= 18) p = 0;                 // dummy row (weights are zero)
        int ic, kh, off;
        if (p < 9) { ic = p / 3; kh = p - 3 * ic; off = 0; }
        else       { int q = p - 9; ic = q / 3; kh = q - 3 * ic; off = 2; }
        return ic * TIC + (wid + kh) * TROW + off + lr;
    };
    const int A00 = pbase(lq);              // chunk0, k = 2lq..
    const int A01 = pbase(lq + 4);          // chunk0, k = 2lq+8..
    const int A10 = pbase(8 + lq);          // chunk1
    const int A11 = pbase(12 + lq);
    const int A2  = pbase(16 + lq);         // k8 tail

    __syncthreads();

    const int Ybase = (by * 8 + wid) * HW;

    // ---- 8 groups of 16 pixels ----
    #pragma unroll
    for (int g = 0; g < 8; ++g) {
        const int o = g * 16;
        float cA[2][4], cB[2][4];
        #pragma unroll
        for (int h = 0; h < 2; ++h)
            #pragma unroll
            for (int i = 0; i < 4; ++i) { cA[h][i] = 0.0f; cB[h][i] = 0.0f; }

        unsigned ah[4], al[4];

        // chunk0 (k16)
        ah[0] = s_pair[A00 + o]; ah[1] = s_pair[A00 + o + 8];
        ah[2] = s_pair[A01 + o]; ah[3] = s_pair[A01 + o + 8];
        al[0] = s_pair[A00 + o + TPAD]; al[1] = s_pair[A00 + o + 8 + TPAD];
        al[2] = s_pair[A01 + o + TPAD]; al[3] = s_pair[A01 + o + 8 + TPAD];
        mma16(cA[0], ah, Bh[0][0][0], Bh[0][0][1]);
        mma16(cA[1], ah, Bh[0][1][0], Bh[0][1][1]);
        mma16(cB[0], ah, Bl[0][0][0], Bl[0][0][1]);
        mma16(cB[1], ah, Bl[0][1][0], Bl[0][1][1]);
        mma16(cB[0], al, Bh[0][0][0], Bh[0][0][1]);
        mma16(cB[1], al, Bh[0][1][0], Bh[0][1][1]);

        // chunk1 (k16)
        ah[0] = s_pair[A10 + o]; ah[1] = s_pair[A10 + o + 8];
        ah[2] = s_pair[A11 + o]; ah[3] = s_pair[A11 + o + 8];
        al[0] = s_pair[A10 + o + TPAD]; al[1] = s_pair[A10 + o + 8 + TPAD];
        al[2] = s_pair[A11 + o + TPAD]; al[3] = s_pair[A11 + o + 8 + TPAD];
        mma16(cA[0], ah, Bh[1][0][0], Bh[1][0][1]);
        mma16(cA[1], ah, Bh[1][1][0], Bh[1][1][1]);
        mma16(cB[0], ah, Bl[1][0][0], Bl[1][0][1]);
        mma16(cB[1], ah, Bl[1][1][0], Bl[1][1][1]);
        mma16(cB[0], al, Bh[1][0][0], Bh[1][0][1]);
        mma16(cB[1], al, Bh[1][1][0], Bh[1][1][1]);

        // chunk2 (k8 tail: pairs 16,17)
        ah[0] = s_pair[A2 + o]; ah[1] = s_pair[A2 + o + 8];
        al[0] = s_pair[A2 + o + TPAD]; al[1] = s_pair[A2 + o + 8 + TPAD];
        mma8(cA[0], ah, B2h[0]);
        mma8(cA[1], ah, B2h[1]);
        mma8(cB[0], ah, B2l[0]);
        mma8(cB[1], ah, B2l[1]);
        mma8(cB[0], al, B2h[0]);
        mma8(cB[1], al, B2h[1]);

        // ---- Store: c0:(lr,2lq) c1:(lr,2lq+1) c2:(lr+8,2lq) c3:(lr+8,2lq+1) ----
        const int X = bx * 128 + o + lr;
        #pragma unroll
        for (int h = 0; h < 2; ++h) {
            float* p = out + (8 * h + 2 * lq) * PLANE + Ybase + X;
            p[0]         = cA[h][0] + cB[h][0];
            p[PLANE]     = cA[h][1] + cB[h][1];
            p[8]         = cA[h][2] + cB[h][2];
            p[PLANE + 8] = cA[h][3] + cB[h][3];
        }
    }
}

extern "C" void kernel_launch(void* const* d_in, const int* in_sizes, int n_in,
                              void* d_out, int out_size) {
    const float* x = (const float*)d_in[0];   // [3, 2048, 2048]
    const float* k = (const float*)d_in[1];   // [16, 3, 3, 3]
    float* out     = (float*)d_out;           // [16, 2048, 2048]

    dim3 grid(HW / 128, HW / 8);              // (16, 256)
    conv3x3_bf16_mma_kernel<<<grid, 256>>>(x, k, out);
}

// round 15
// speedup vs baseline: 1.0962x; 1.0010x over previous
#include <cuda_runtime.h>
#include <cuda_bf16.h>
#include <cstdint>

// Conv2d: x[3,2048,2048] fp32 * k[16,3,3,3] fp32, pad=1, stride=1 -> out[16,2048,2048]
//
// R15 (v10): implicit-GEMM, mma.sync.m16n8k16.bf16, 3-term split, K packed to 32.
//   K-slot map (16 u64 slots, each = 2 k):
//     slots 0-8 : main pairs (kw0,kw1) of (ic,kh), slot p=(ic*3+kh)
//     slots 9-11: P[kh] = (ic0 kw2, ic1 kw2)   (cross-channel kw2 pairing)
//     slots 12-14: S[kh] = (ic2 kw2, 0)
//     slot 15   : zero weights (dummy address)
//   Each u64 smem slot = [bf16hi(v0), bf16hi(v1), bf16lo(v0), bf16lo(v1)] ->
//   ONE LDS.64 yields both the hi and lo A-fragment registers.
//   Slot-row base addresses engineered to mod-16 classes {0,4,8,12} so every
//   16-lane LDS.64 phase is bank-conflict-free.
//   Per 16-px group: 12 MMA + 8 LDS.64 (was 18 MMA + 20 LDS.32 in v9).
//   CTA 256 thr = 8 warps (warp = tile row), tile 8x128x16oc, 4 CTAs/SM.

#define HW    2048
#define PLANE (2048 * 2048)

// u64-slot layout constants (indices in u64 units)
#define MPL   1324         // M plane stride  (>=1320, mod16 = 12 -> ic class step)
#define MRS   132          // row stride      (mod16 = 4 -> kh class step)
#define PBASE 3972         // >= 3966, mod16 = 4
#define SBASE 5300         // >= 5288, mod16 = 4
#define NU64  6616
#define SMEM_BYTES (NU64 * 8)

__device__ __forceinline__ void mma16(float* c, const unsigned* a,
                                      unsigned b0, unsigned b1) {
    asm volatile(
        "mma.sync.aligned.m16n8k16.row.col.f32.bf16.bf16.f32 "
        "{%0,%1,%2,%3}, {%4,%5,%6,%7}, {%8,%9}, {%0,%1,%2,%3};"
        : "+f"(c[0]), "+f"(c[1]), "+f"(c[2]), "+f"(c[3])
        : "r"(a[0]), "r"(a[1]), "r"(a[2]), "r"(a[3]), "r"(b0), "r"(b1));
}

// Weight pair for K-slot p, output channel oc -> packed bf16x2 hi & lo parts.
__device__ __forceinline__ void wpair(const float* kern, int p, int oc,
                                      unsigned& bh, unsigned& bl) {
    float wa = 0.0f, wb = 0.0f;
    if (p < 9) {                      // (ic,kh): kw0, kw1
        int ic = p / 3, kh = p - 3 * ic;
        const float* kp = kern + oc * 27 + ic * 9 + kh * 3;
        wa = kp[0];
        wb = kp[1];
    } else if (p < 12) {              // P: (ic0 kw2, ic1 kw2)
        int kh = p - 9;
        wa = kern[oc * 27 + 0 + kh * 3 + 2];
        wb = kern[oc * 27 + 9 + kh * 3 + 2];
    } else if (p < 15) {              // S: (ic2 kw2, 0)
        int kh = p - 12;
        wa = kern[oc * 27 + 18 + kh * 3 + 2];
    }                                 // p == 15: zeros
    __nv_bfloat16 wah = __float2bfloat16(wa);
    __nv_bfloat16 wbh = __float2bfloat16(wb);
    unsigned la = __bfloat16_as_ushort(__float2bfloat16(wa - __bfloat162float(wah)));
    unsigned lb = __bfloat16_as_ushort(__float2bfloat16(wb - __bfloat162float(wbh)));
    bh = (unsigned)__bfloat16_as_ushort(wah)
       | ((unsigned)__bfloat16_as_ushort(wbh) << 16);
    bl = la | (lb << 16);
}

__global__ __launch_bounds__(256, 4)
void conv3x3_bf16_k32_kernel(const float* __restrict__ x,
                             const float* __restrict__ kern,
                             float* __restrict__ out) {
    extern __shared__ unsigned long long S64[];
    unsigned short* sh = reinterpret_cast<unsigned short*>(S64);
    unsigned*       s32 = reinterpret_cast<unsigned*>(S64);

    const int tid  = threadIdx.x;
    const int bx   = blockIdx.x;            // 16 tiles of 128 cols
    const int by   = blockIdx.y;            // 256 tiles of 8 rows
    const int row0 = by * 8 - 1;
    const int col0 = bx * 128 - 1;
    const int wid  = tid >> 5;              // warp = output row in tile (0..7)
    const int lane = tid & 31;
    const int lq   = lane & 3;
    const int lr   = lane >> 2;

    // ---- B fragments from gmem (before sync): chunk0 slots {lq,4+lq},
    //      chunk1 slots {8+lq,12+lq}; halves h: oc = 8h+lr ----
    unsigned Wh[2][2][2], Wl[2][2][2];
    #pragma unroll
    for (int ch = 0; ch < 2; ++ch)
        #pragma unroll
        for (int h = 0; h < 2; ++h) {
            wpair(kern, 8 * ch + lq,     8 * h + lr, Wh[ch][h][0], Wl[ch][h][0]);
            wpair(kern, 8 * ch + 4 + lq, 8 * h + lr, Wh[ch][h][1], Wl[ch][h][1]);
        }

    // ---- Stage input tile: 3 ic x 10 rows x 130 cols ----
    for (int i = tid; i < 3900; i += 256) {
        int ic  = i / 1300;
        int rem = i - ic * 1300;
        int r   = rem / 130;
        int c   = rem - r * 130;            // 0..129
        int gy = row0 + r;
        int gx = col0 + c;
        float v = 0.0f;
        if ((unsigned)gy < (unsigned)HW && (unsigned)gx < (unsigned)HW)
            v = x[ic * PLANE + gy * HW + gx];
        __nv_bfloat16 hb = __float2bfloat16(v);
        unsigned short hu = __bfloat16_as_ushort(hb);
        unsigned short lu = __bfloat16_as_ushort(
            __float2bfloat16(v - __bfloat162float(hb)));

        int m = ic * MPL + r * MRS + c;     // main slot: half0 of slot c
        sh[4 * m + 0] = hu;
        sh[4 * m + 2] = lu;
        if (c > 0) {                        // half1 of slot c-1
            sh[4 * (m - 1) + 1] = hu;
            sh[4 * (m - 1) + 3] = lu;
        }
        if (c >= 2) {
            int q = r * MRS + (c - 2);
            if (ic == 0) {
                int t = PBASE + q;
                sh[4 * t + 0] = hu; sh[4 * t + 2] = lu;
            } else if (ic == 1) {
                int t = PBASE + q;
                sh[4 * t + 1] = hu; sh[4 * t + 3] = lu;
            } else {
                int t = SBASE + q;          // (hi,0) and (lo,0) as u32 stores
                s32[2 * t + 0] = (unsigned)hu;
                s32[2 * t + 1] = (unsigned)lu;
            }
        }
    }

    // ---- A slot base addresses (u64 index incl. lr) ----
    auto slot_addr = [&](int p) -> int {
        if (p < 9)  return (p / 3) * MPL + (wid + p % 3) * MRS + lr;
        if (p < 12) return PBASE + (wid + (p - 9)) * MRS + lr;
        if (p < 15) return SBASE + (wid + (p - 12)) * MRS + lr;
        return lr;                          // zero-weight slot, class 0
    };
    const int I00 = slot_addr(lq);
    const int I01 = slot_addr(4 + lq);
    const int I10 = slot_addr(8 + lq);
    const int I11 = slot_addr(12 + lq);

    __syncthreads();

    const int Ybase = (by * 8 + wid) * HW;

    // ---- 8 groups of 16 pixels ----
    #pragma unroll
    for (int g = 0; g < 8; ++g) {
        const int o = g * 16;
        float cA[2][4], cB[2][4];
        #pragma unroll
        for (int h = 0; h < 2; ++h)
            #pragma unroll
            for (int i = 0; i < 4; ++i) { cA[h][i] = 0.0f; cB[h][i] = 0.0f; }

        unsigned ah[4], al[4];

        // chunk 0
        {
            unsigned long long q0 = S64[I00 + o];
            unsigned long long q1 = S64[I00 + o + 8];
            unsigned long long q2 = S64[I01 + o];
            unsigned long long q3 = S64[I01 + o + 8];
            ah[0] = (unsigned)q0; al[0] = (unsigned)(q0 >> 32);
            ah[1] = (unsigned)q1; al[1] = (unsigned)(q1 >> 32);
            ah[2] = (unsigned)q2; al[2] = (unsigned)(q2 >> 32);
            ah[3] = (unsigned)q3; al[3] = (unsigned)(q3 >> 32);
            #pragma unroll
            for (int h = 0; h < 2; ++h) {
                mma16(cA[h], ah, Wh[0][h][0], Wh[0][h][1]);   // hi * whi
                mma16(cB[h], ah, Wl[0][h][0], Wl[0][h][1]);   // hi * wlo
                mma16(cB[h], al, Wh[0][h][0], Wh[0][h][1]);   // lo * whi
            }
        }
        // chunk 1
        {
            unsigned long long q0 = S64[I10 + o];
            unsigned long long q1 = S64[I10 + o + 8];
            unsigned long long q2 = S64[I11 + o];
            unsigned long long q3 = S64[I11 + o + 8];
            ah[0] = (unsigned)q0; al[0] = (unsigned)(q0 >> 32);
            ah[1] = (unsigned)q1; al[1] = (unsigned)(q1 >> 32);
            ah[2] = (unsigned)q2; al[2] = (unsigned)(q2 >> 32);
            ah[3] = (unsigned)q3; al[3] = (unsigned)(q3 >> 32);
            #pragma unroll
            for (int h = 0; h < 2; ++h) {
                mma16(cA[h], ah, Wh[1][h][0], Wh[1][h][1]);
                mma16(cB[h], ah, Wl[1][h][0], Wl[1][h][1]);
                mma16(cB[h], al, Wh[1][h][0], Wh[1][h][1]);
            }
        }

        // ---- Store: c0:(lr, oc 2lq) c1:(lr, 2lq+1) c2:(lr+8, 2lq) c3:(lr+8, 2lq+1)
        const int X = bx * 128 + o + lr;
        #pragma unroll
        for (int h = 0; h < 2; ++h) {
            float* p = out + (8 * h + 2 * lq) * PLANE + Ybase + X;
            p[0]         = cA[h][0] + cB[h][0];
            p[PLANE]     = cA[h][1] + cB[h][1];
            p[8]         = cA[h][2] + cB[h][2];
            p[PLANE + 8] = cA[h][3] + cB[h][3];
        }
    }
}

extern "C" void kernel_launch(void* const* d_in, const int* in_sizes, int n_in,
                              void* d_out, int out_size) {
    const float* x = (const float*)d_in[0];   // [3, 2048, 2048]
    const float* k = (const float*)d_in[1];   // [16, 3, 3, 3]
    float* out     = (float*)d_out;           // [16, 2048, 2048]

    cudaFuncSetAttribute(conv3x3_bf16_k32_kernel,
                         cudaFuncAttributeMaxDynamicSharedMemorySize, SMEM_BYTES);
    dim3 grid(HW / 128, HW / 8);              // (16, 256)
    conv3x3_bf16_k32_kernel<<<grid, 256, SMEM_BYTES>>>(x, k, out);
}

// round 16
// speedup vs baseline: 1.6883x; 1.5402x over previous
#include <cuda_runtime.h>
#include <cuda_bf16.h>
#include <cstdint>

// Conv2d: x[3,2048,2048] fp32 * k[16,3,3,3] fp32, pad=1, stride=1 -> out[16,2048,2048]
//
// R16 (v11): v10's bf16 m16n8k16 implicit-GEMM (K=32 slot map, validated) with a
// rebuilt prologue:
//   - packed weight table staged ONCE into smem (256 thr x 1 entry), consumers
//     fetch with 8 LDS.64 (was: 16 wpair computations per thread, ~190 issues).
//   - input staging by (row, 32-col segment) per warp: no divisions; per value-pair
//     ONE PRMT builds the bf16-hi pair (truncated-hi split), ONE cvt.rn.bf16x2.f32
//     builds the lo pair, ONE STS.64 writes the slot. 5 STS.64 / 6 values.
//   - main loop / K-slot map / epilogue identical to v10 (rel_err 4.4e-6 class).

#define HW    2048
#define PLANE (2048 * 2048)

// u64-slot layout (u64 units)
#define MPL   1324
#define MRS   132
#define PBASE 3972
#define SBASE 5300
#define WBASE 6616          // weight table: 16 slots x 16 oc
#define NU64  6872
#define SMEM_BYTES (NU64 * 8)

typedef unsigned long long u64;

__device__ __forceinline__ void mma16(float* c, const unsigned* a,
                                      unsigned b0, unsigned b1) {
    asm volatile(
        "mma.sync.aligned.m16n8k16.row.col.f32.bf16.bf16.f32 "
        "{%0,%1,%2,%3}, {%4,%5,%6,%7}, {%8,%9}, {%0,%1,%2,%3};"
        : "+f"(c[0]), "+f"(c[1]), "+f"(c[2]), "+f"(c[3])
        : "r"(a[0]), "r"(a[1]), "r"(a[2]), "r"(a[3]), "r"(b0), "r"(b1));
}

__device__ __forceinline__ unsigned prmt(unsigned a, unsigned b, unsigned sel) {
    unsigned r;
    asm("prmt.b32 %0, %1, %2, %3;" : "=r"(r) : "r"(a), "r"(b), "r"(sel));
    return r;
}

// (bf16(hi_val) << 16) | bf16(lo_val)
__device__ __forceinline__ unsigned bf16x2(float hi_val, float lo_val) {
    unsigned r;
    asm("cvt.rn.bf16x2.f32 %0, %1, %2;" : "=r"(r) : "f"(hi_val), "f"(lo_val));
    return r;
}

// Weight pair for K-slot p, oc -> (bh = bf16x2 hi parts, bl = lo parts), rounded.
__device__ __forceinline__ void wpair(const float* kern, int p, int oc,
                                      unsigned& bh, unsigned& bl) {
    float wa = 0.0f, wb = 0.0f;
    if (p < 9) {
        int ic = p / 3, kh = p - 3 * ic;
        const float* kp = kern + oc * 27 + ic * 9 + kh * 3;
        wa = kp[0]; wb = kp[1];
    } else if (p < 12) {
        int kh = p - 9;
        wa = kern[oc * 27 + 0 + kh * 3 + 2];
        wb = kern[oc * 27 + 9 + kh * 3 + 2];
    } else if (p < 15) {
        int kh = p - 12;
        wa = kern[oc * 27 + 18 + kh * 3 + 2];
    }
    __nv_bfloat16 wah = __float2bfloat16(wa);
    __nv_bfloat16 wbh = __float2bfloat16(wb);
    float ra = wa - __bfloat162float(wah);
    float rb = wb - __bfloat162float(wbh);
    bh = (unsigned)__bfloat16_as_ushort(wah)
       | ((unsigned)__bfloat16_as_ushort(wbh) << 16);
    bl = bf16x2(rb, ra);
}

__global__ __launch_bounds__(256, 4)
void conv3x3_bf16_v11_kernel(const float* __restrict__ x,
                             const float* __restrict__ kern,
                             float* __restrict__ out) {
    extern __shared__ u64 S64[];
    uint2* S2 = reinterpret_cast<uint2*>(S64);

    const int tid  = threadIdx.x;
    const int bx   = blockIdx.x;            // 16 tiles of 128 cols
    const int by   = blockIdx.y;            // 256 tiles of 8 rows
    const int row0 = by * 8 - 1;
    const int col0 = bx * 128 - 1;
    const int warp = tid >> 5;              // 8 warps; warp = output row in tile
    const int lane = tid & 31;
    const int lq   = lane & 3;
    const int lr   = lane >> 2;

    // ---- Stage weight table: 16 slots x 16 oc, one entry per thread ----
    {
        int p  = tid >> 4;
        int oc = tid & 15;
        unsigned bh, bl;
        wpair(kern, p, oc, bh, bl);
        S2[WBASE + tid] = make_uint2(bh, bl);
    }

    // ---- Stage input tile: 40 (row, seg32) units + 20-unit tail ----
    // Value v[ic][r][c], c = 0..129 (gx = col0 + c). Truncated-hi bf16 split.
    #pragma unroll
    for (int i = 0; i < 5; ++i) {
        int u = warp + 8 * i;               // 0..39
        int r = u >> 2;                     // 0..9
        int c = ((u & 3) << 5) + lane;      // 0..127
        int gy = row0 + r;
        int gx = col0 + c;
        bool rok = (unsigned)gy < (unsigned)HW;
        const float* base = x + gy * HW;

        unsigned ua[3], ub[3];              // bits of v[c], v[c+1] per ic
        float la[3], lb[3];                 // lo residuals
        #pragma unroll
        for (int ic = 0; ic < 3; ++ic) {
            float va = (rok && (unsigned)gx < (unsigned)HW)
                       ? base[ic * PLANE + gx] : 0.0f;
            float vb = (rok && (unsigned)(gx + 1) < (unsigned)HW)
                       ? base[ic * PLANE + gx + 1] : 0.0f;
            ua[ic] = __float_as_uint(va);
            ub[ic] = __float_as_uint(vb);
            la[ic] = va - __uint_as_float(ua[ic] & 0xFFFF0000u);
            lb[ic] = vb - __uint_as_float(ub[ic] & 0xFFFF0000u);
        }

        // main slots: (v[c], v[c+1]) for each ic
        #pragma unroll
        for (int ic = 0; ic < 3; ++ic) {
            unsigned hp = prmt(ua[ic], ub[ic], 0x7632);
            unsigned lp = bf16x2(lb[ic], la[ic]);
            S2[ic * MPL + r * MRS + c] = make_uint2(hp, lp);
        }
        // P slot q = c-2: (x0[c], x1[c]);  S slot q = c-2: (x2[c], 0)
        if (c >= 2) {
            unsigned hp = prmt(ua[0], ua[1], 0x7632);
            unsigned lp = bf16x2(la[1], la[0]);
            S2[PBASE + r * MRS + (c - 2)] = make_uint2(hp, lp);
            unsigned hs = ua[2] >> 16;
            unsigned ls = bf16x2(0.0f, la[2]);
            S2[SBASE + r * MRS + (c - 2)] = make_uint2(hs, ls);
        }
    }
    // tail: c = 128, 129 -> P slots 126,127 and S slots 126,127
    if (tid < 20) {
        int r = tid >> 1;
        int c = 128 + (tid & 1);
        int gy = row0 + r;
        int gx = col0 + c;
        bool ok = (unsigned)gy < (unsigned)HW && (unsigned)gx < (unsigned)HW;
        float v0 = ok ? x[0 * PLANE + gy * HW + gx] : 0.0f;
        float v1 = ok ? x[1 * PLANE + gy * HW + gx] : 0.0f;
        float v2 = ok ? x[2 * PLANE + gy * HW + gx] : 0.0f;
        unsigned u0 = __float_as_uint(v0), u1 = __float_as_uint(v1),
                 u2 = __float_as_uint(v2);
        float l0 = v0 - __uint_as_float(u0 & 0xFFFF0000u);
        float l1 = v1 - __uint_as_float(u1 & 0xFFFF0000u);
        float l2 = v2 - __uint_as_float(u2 & 0xFFFF0000u);
        S2[PBASE + r * MRS + (c - 2)] =
            make_uint2(prmt(u0, u1, 0x7632), bf16x2(l1, l0));
        S2[SBASE + r * MRS + (c - 2)] =
            make_uint2(u2 >> 16, bf16x2(0.0f, l2));
    }

    __syncthreads();

    // ---- B fragments from the smem weight table (8 LDS.64) ----
    unsigned Wh[2][2][2], Wl[2][2][2];
    #pragma unroll
    for (int ch = 0; ch < 2; ++ch)
        #pragma unroll
        for (int h = 0; h < 2; ++h) {
            uint2 w0 = S2[WBASE + (8 * ch + lq) * 16 + 8 * h + lr];
            uint2 w1 = S2[WBASE + (8 * ch + 4 + lq) * 16 + 8 * h + lr];
            Wh[ch][h][0] = w0.x; Wl[ch][h][0] = w0.y;
            Wh[ch][h][1] = w1.x; Wl[ch][h][1] = w1.y;
        }

    // ---- A slot base addresses (u64 index incl. lr) ----
    auto slot_addr = [&](int p) -> int {
        if (p < 9)  return (p / 3) * MPL + (warp + p % 3) * MRS + lr;
        if (p < 12) return PBASE + (warp + (p - 9)) * MRS + lr;
        if (p < 15) return SBASE + (warp + (p - 12)) * MRS + lr;
        return lr;                          // zero-weight slot (finite data)
    };
    const int I00 = slot_addr(lq);
    const int I01 = slot_addr(4 + lq);
    const int I10 = slot_addr(8 + lq);
    const int I11 = slot_addr(12 + lq);

    const int Ybase = (by * 8 + warp) * HW;

    // ---- 8 groups of 16 pixels ----
    #pragma unroll
    for (int g = 0; g < 8; ++g) {
        const int o = g * 16;
        float cA[2][4], cB[2][4];
        #pragma unroll
        for (int h = 0; h < 2; ++h)
            #pragma unroll
            for (int i = 0; i < 4; ++i) { cA[h][i] = 0.0f; cB[h][i] = 0.0f; }

        unsigned ah[4], al[4];
        {   // chunk 0
            uint2 q0 = S2[I00 + o], q1 = S2[I00 + o + 8];
            uint2 q2 = S2[I01 + o], q3 = S2[I01 + o + 8];
            ah[0] = q0.x; al[0] = q0.y;
            ah[1] = q1.x; al[1] = q1.y;
            ah[2] = q2.x; al[2] = q2.y;
            ah[3] = q3.x; al[3] = q3.y;
            #pragma unroll
            for (int h = 0; h < 2; ++h) {
                mma16(cA[h], ah, Wh[0][h][0], Wh[0][h][1]);
                mma16(cB[h], ah, Wl[0][h][0], Wl[0][h][1]);
                mma16(cB[h], al, Wh[0][h][0], Wh[0][h][1]);
            }
        }
        {   // chunk 1
            uint2 q0 = S2[I10 + o], q1 = S2[I10 + o + 8];
            uint2 q2 = S2[I11 + o], q3 = S2[I11 + o + 8];
            ah[0] = q0.x; al[0] = q0.y;
            ah[1] = q1.x; al[1] = q1.y;
            ah[2] = q2.x; al[2] = q2.y;
            ah[3] = q3.x; al[3] = q3.y;
            #pragma unroll
            for (int h = 0; h < 2; ++h) {
                mma16(cA[h], ah, Wh[1][h][0], Wh[1][h][1]);
                mma16(cB[h], ah, Wl[1][h][0], Wl[1][h][1]);
                mma16(cB[h], al, Wh[1][h][0], Wh[1][h][1]);
            }
        }

        // ---- Store: c0:(lr, oc 2lq) c1:(lr, 2lq+1) c2:(lr+8, 2lq) c3:(lr+8, 2lq+1)
        const int X = bx * 128 + o + lr;
        #pragma unroll
        for (int h = 0; h < 2; ++h) {
            float* p = out + (8 * h + 2 * lq) * PLANE + Ybase + X;
            p[0]         = cA[h][0] + cB[h][0];
            p[PLANE]     = cA[h][1] + cB[h][1];
            p[8]         = cA[h][2] + cB[h][2];
            p[PLANE + 8] = cA[h][3] + cB[h][3];
        }
    }
}

extern "C" void kernel_launch(void* const* d_in, const int* in_sizes, int n_in,
                              void* d_out, int out_size) {
    const float* x = (const float*)d_in[0];   // [3, 2048, 2048]
    const float* k = (const float*)d_in[1];   // [16, 3, 3, 3]
    float* out     = (float*)d_out;           // [16, 2048, 2048]

    cudaFuncSetAttribute(conv3x3_bf16_v11_kernel,
                         cudaFuncAttributeMaxDynamicSharedMemorySize, SMEM_BYTES);
    dim3 grid(HW / 128, HW / 8);              // (16, 256)
    conv3x3_bf16_v11_kernel<<<grid, 256, SMEM_BYTES>>>(x, k, out);
}